// round 2
// baseline (speedup 1.0000x reference)
#include <cuda_runtime.h>

// CenterLoss collapses: mask is one-hot on labels, so only distmat[i, labels[i]]
// survives; the other (B*C - B) masked zeros each clamp to 1e-12 (a constant).
// loss = ( sum_i clamp(||x_i - c_{labels[i]}||^2, 1e-12, 1e12) + (B*C-B)*1e-12 ) / B
//
// Single-kernel version: last-block-done pattern replaces the separate
// finalize launch (which cost 4.4us of the 6.9us total in R1).

#define BATCH     1024
#define NUM_CLASS 100000
#define FEAT      128

#define NBLK 128   // 128 blocks * 8 warps = 1024 warps = 1 warp per row

__device__ float        g_partials[NBLK];
__device__ unsigned int g_count = 0;   // reset by the finishing block each call

__global__ void __launch_bounds__(256)
center_loss_fused(const float* __restrict__ x,
                  const int*   __restrict__ labels,
                  const float* __restrict__ centers,
                  float*       __restrict__ out) {
    const int warp = threadIdx.x >> 5;
    const int lane = threadIdx.x & 31;
    const int row  = blockIdx.x * 8 + warp;   // 0..1023

    const int lab = labels[row];

    // 128 floats per row = 32 lanes * float4
    const float4 a = reinterpret_cast<const float4*>(x       + (size_t)row * FEAT)[lane];
    const float4 b = reinterpret_cast<const float4*>(centers + (size_t)lab * FEAT)[lane];

    const float d0 = a.x - b.x;
    const float d1 = a.y - b.y;
    const float d2 = a.z - b.z;
    const float d3 = a.w - b.w;
    float s = d0 * d0 + d1 * d1 + d2 * d2 + d3 * d3;

    // warp reduce -> full ||x - c||^2 for this row
    #pragma unroll
    for (int off = 16; off; off >>= 1)
        s += __shfl_xor_sync(0xffffffffu, s, off);

    // clamp (matches jnp.clip on the surviving diagonal entry)
    s = fminf(fmaxf(s, 1e-12f), 1e12f);

    // deterministic block reduce over the 8 warps
    __shared__ float sm[8];
    __shared__ bool  is_last;
    if (lane == 0) sm[warp] = s;
    __syncthreads();

    if (threadIdx.x == 0) {
        float t = 0.0f;
        #pragma unroll
        for (int i = 0; i < 8; i++) t += sm[i];
        g_partials[blockIdx.x] = t;
        __threadfence();                       // publish partial before count bump
        unsigned int prev = atomicAdd(&g_count, 1u);
        is_last = (prev == NBLK - 1);
    }
    __syncthreads();

    // Last block to finish: fold the 128 partials in a FIXED order (deterministic),
    // add the clamp constant, write the scalar, reset the counter for next replay.
    if (is_last && warp == 0) {
        __threadfence();                       // acquire: see all g_partials writes
        float v = g_partials[lane] + g_partials[lane + 32]
                + g_partials[lane + 64] + g_partials[lane + 96];
        #pragma unroll
        for (int off = 16; off; off >>= 1)
            v += __shfl_xor_sync(0xffffffffu, v, off);
        if (lane == 0) {
            const double extra = (double)((long long)BATCH * (long long)NUM_CLASS
                                          - (long long)BATCH) * 1e-12;
            out[0] = (float)(((double)v + extra) / (double)BATCH);
            __threadfence();
            g_count = 0;                       // ready for next graph replay
        }
    }
}

extern "C" void kernel_launch(void* const* d_in, const int* in_sizes, int n_in,
                              void* d_out, int out_size) {
    const float* x       = (const float*)d_in[0];
    const int*   labels  = (const int*)  d_in[1];
    const float* centers = (const float*)d_in[2];
    float*       out     = (float*)d_out;

    center_loss_fused<<<NBLK, 256>>>(x, labels, centers, out);
}

// round 4
// speedup vs baseline: 1.3333x; 1.3333x over previous
#include <cuda_runtime.h>

// CenterLoss collapses: mask is one-hot on labels, so only distmat[i, labels[i]]
// survives; the other (B*C - B) masked zeros each clamp to 1e-12 (a constant).
// loss = ( sum_i clamp(||x_i - c_{labels[i]}||^2, 1e-12, 1e12) + (B*C-B)*1e-12 ) / B
//
// R3 retry (previous round hit a GPU-broker timeout, no data):
//  - deterministic u64 fixed-point atomic (REDG) replaces partials array + fences
//  - PDL (programmatic stream serialization) hides the finalize launch gap

#define BATCH     1024
#define NUM_CLASS 100000
#define FEAT      128

#define NBLK 128   // 128 blocks * 8 warps = 1024 warps = 1 warp per row

// Fixed-point accumulator: block partial < 2^13, scale 2^32 -> sum < 2^52. Exact
// integer addition is order-independent => deterministic across replays.
__device__ unsigned long long g_fixed = 0ULL;

__global__ void __launch_bounds__(256)
center_loss_rows(const float* __restrict__ x,
                 const int*   __restrict__ labels,
                 const float* __restrict__ centers) {
    const int warp = threadIdx.x >> 5;
    const int lane = threadIdx.x & 31;
    const int row  = blockIdx.x * 8 + warp;   // 0..1023

    const int lab = labels[row];

    // 128 floats per row = 32 lanes * float4
    const float4 a = reinterpret_cast<const float4*>(x       + (size_t)row * FEAT)[lane];
    const float4 b = reinterpret_cast<const float4*>(centers + (size_t)lab * FEAT)[lane];

    const float d0 = a.x - b.x;
    const float d1 = a.y - b.y;
    const float d2 = a.z - b.z;
    const float d3 = a.w - b.w;
    float s = d0 * d0 + d1 * d1 + d2 * d2 + d3 * d3;

    // warp reduce -> full ||x - c||^2 for this row
    #pragma unroll
    for (int off = 16; off; off >>= 1)
        s += __shfl_xor_sync(0xffffffffu, s, off);

    // clamp (matches jnp.clip on the surviving diagonal entry)
    s = fminf(fmaxf(s, 1e-12f), 1e12f);

    // deterministic block reduce over the 8 warps
    __shared__ float sm[8];
    if (lane == 0) sm[warp] = s;
    __syncthreads();

    if (threadIdx.x == 0) {
        float t = 0.0f;
        #pragma unroll
        for (int i = 0; i < 8; i++) t += sm[i];
        // fixed-point, exact commutative accumulation (REDG, no return needed)
        unsigned long long v = (unsigned long long)((double)t * 4294967296.0);
        atomicAdd(&g_fixed, v);
    }
    // allow the dependent (finalize) kernel to launch; its griddepcontrol.wait
    // still observes all of this grid's memory ops.
    asm volatile("griddepcontrol.launch_dependents;");
}

__global__ void __launch_bounds__(32)
center_loss_final(float* __restrict__ out) {
    // wait for the rows grid's memory operations to be visible
    asm volatile("griddepcontrol.wait;" ::: "memory");
    if (threadIdx.x == 0) {
        unsigned long long fix = g_fixed;
        const double sum = (double)fix * (1.0 / 4294967296.0);
        const double extra = (double)((long long)BATCH * (long long)NUM_CLASS
                                      - (long long)BATCH) * 1e-12;
        out[0] = (float)((sum + extra) / (double)BATCH);
        g_fixed = 0ULL;   // reset for next graph replay
    }
}

extern "C" void kernel_launch(void* const* d_in, const int* in_sizes, int n_in,
                              void* d_out, int out_size) {
    const float* x       = (const float*)d_in[0];
    const int*   labels  = (const int*)  d_in[1];
    const float* centers = (const float*)d_in[2];
    float*       out     = (float*)d_out;

    center_loss_rows<<<NBLK, 256>>>(x, labels, centers);

    // Finalize with programmatic stream serialization: launch overlaps the rows
    // kernel; griddepcontrol.wait inside provides the ordering.
    cudaLaunchConfig_t cfg = {};
    cfg.gridDim  = dim3(1, 1, 1);
    cfg.blockDim = dim3(32, 1, 1);
    cfg.dynamicSmemBytes = 0;
    cfg.stream = 0;
    cudaLaunchAttribute attr[1];
    attr[0].id = cudaLaunchAttributeProgrammaticStreamSerialization;
    attr[0].val.programmaticStreamSerializationAllowed = 1;
    cfg.attrs = attr;
    cfg.numAttrs = 1;
    cudaLaunchKernelEx(&cfg, center_loss_final, out);
}

// round 5
// speedup vs baseline: 1.3913x; 1.0435x over previous
#include <cuda_runtime.h>

// CenterLoss collapses: mask is one-hot on labels, so only distmat[i, labels[i]]
// survives; the other (B*C - B) masked zeros each clamp to 1e-12 (a constant).
// loss = ( sum_i clamp(||x_i - c_{labels[i]}||^2, 1e-12, 1e12) + (B*C-B)*1e-12 ) / B
//
// R5: SINGLE kernel node (any 2nd graph node costs ~4.4us on this harness, and
// PDL doesn't hide it). Fusion without fences:
//   - block partial -> u64 fixed-point (scale 2^32): exact, order-independent
//   - one atomicAdd per block to a single u64 that packs {count : bits>=57,
//     sum : bits<57}. Same-address RMWs are totally ordered, so the block whose
//     RETURNED count == NBLK-1 holds the full sum of all other blocks in the
//     returned low bits. No __threadfence, no partials array, no re-read.
//   - that one thread finalizes and resets the accumulator (kernel boundary
//     orders the reset for the next graph replay).

#define BATCH     1024
#define NUM_CLASS 100000
#define FEAT      128

#define NBLK 128           // 128 blocks * 8 warps = 1024 warps = 1 warp per row
#define CNT_SHIFT 57       // count lives in bits [57,64); sum in bits [0,57)
#define SUM_MASK  ((1ULL << CNT_SHIFT) - 1ULL)

__device__ unsigned long long g_acc = 0ULL;   // {count, fixed-point sum}

__global__ void __launch_bounds__(256)
center_loss_onepass(const float* __restrict__ x,
                    const int*   __restrict__ labels,
                    const float* __restrict__ centers,
                    float*       __restrict__ out) {
    const int warp = threadIdx.x >> 5;
    const int lane = threadIdx.x & 31;
    const int row  = blockIdx.x * 8 + warp;   // 0..1023

    const int lab = labels[row];

    // 128 floats per row = 32 lanes * float4
    const float4 a = reinterpret_cast<const float4*>(x       + (size_t)row * FEAT)[lane];
    const float4 b = reinterpret_cast<const float4*>(centers + (size_t)lab * FEAT)[lane];

    const float d0 = a.x - b.x;
    const float d1 = a.y - b.y;
    const float d2 = a.z - b.z;
    const float d3 = a.w - b.w;
    float s = d0 * d0 + d1 * d1 + d2 * d2 + d3 * d3;

    // warp reduce -> full ||x - c||^2 for this row
    #pragma unroll
    for (int off = 16; off; off >>= 1)
        s += __shfl_xor_sync(0xffffffffu, s, off);

    // clamp (matches jnp.clip on the surviving diagonal entry)
    s = fminf(fmaxf(s, 1e-12f), 1e12f);

    // deterministic block reduce over the 8 warps (shared mem, fixed order)
    __shared__ float sm[8];
    if (lane == 0) sm[warp] = s;
    __syncthreads();

    if (threadIdx.x == 0) {
        float t = 0.0f;
        #pragma unroll
        for (int i = 0; i < 8; i++) t += sm[i];

        // exact fixed-point contribution + count tick in one atomic
        const unsigned long long fix =
            (unsigned long long)((double)t * 4294967296.0);      // * 2^32
        const unsigned long long packed = fix | (1ULL << CNT_SHIFT);
        const unsigned long long prev = atomicAdd(&g_acc, packed);

        if ((prev >> CNT_SHIFT) == (unsigned long long)(NBLK - 1)) {
            // we are the last block: prev's low bits hold everyone else's sum
            const unsigned long long total = (prev + packed) & SUM_MASK;
            const double sum = (double)total * (1.0 / 4294967296.0);
            const double extra = (double)((long long)BATCH * (long long)NUM_CLASS
                                          - (long long)BATCH) * 1e-12;
            out[0] = (float)((sum + extra) / (double)BATCH);
            // reset for next graph replay (kernel boundary publishes it)
            atomicExch(&g_acc, 0ULL);
        }
    }
}

extern "C" void kernel_launch(void* const* d_in, const int* in_sizes, int n_in,
                              void* d_out, int out_size) {
    const float* x       = (const float*)d_in[0];
    const int*   labels  = (const int*)  d_in[1];
    const float* centers = (const float*)d_in[2];
    float*       out     = (float*)d_out;

    center_loss_onepass<<<NBLK, 256>>>(x, labels, centers, out);
}